// round 11
// baseline (speedup 1.0000x reference)
#include <cuda_runtime.h>
#include <cuda_fp16.h>
#include <cstdint>
#include <cstddef>

#define NB 128
#define NS 512
#define ND 128
#define NH 1024
#define NO 64
#define NIN 257
#define KP 264
#define NG 4096

// ---------------- device scratch ----------------
__device__ __align__(16) float d_xt[NS * NB * KP];
__device__ __align__(16) float d_wih[NG * KP];
__device__ __align__(16) __half d_whh16[NG * NH];
__device__ __align__(16) float d_bias[NG];
__device__ __align__(16) __half d_xg16[(size_t)NS * NB * NG];  // fp16 input-gate precompute
__device__ __align__(1024) __half d_h16[2][NB * NH];   // permuted+swizzled layout
__device__ __align__(16) int d_pflag[128 * 8];         // producer step flags (stride 8)

// ---------------- helpers ----------------
__device__ __forceinline__ unsigned smem_u32(const void* p) {
    return (unsigned)__cvta_generic_to_shared(p);
}
__device__ __forceinline__ void cpa16(unsigned s, const void* g) {
    asm volatile("cp.async.cg.shared.global [%0], [%1], 16;\n" :: "r"(s), "l"(g));
}
__device__ __forceinline__ void cp_commit() { asm volatile("cp.async.commit_group;\n"); }
__device__ __forceinline__ void cp_wait0() { asm volatile("cp.async.wait_group 0;\n" ::: "memory"); }
__device__ __forceinline__ void cp_wait1() { asm volatile("cp.async.wait_group 1;\n" ::: "memory"); }
__device__ __forceinline__ void cp_wait2() { asm volatile("cp.async.wait_group 2;\n" ::: "memory"); }
__device__ __forceinline__ void cp_wait3() { asm volatile("cp.async.wait_group 3;\n" ::: "memory"); }

__device__ __forceinline__ float to_tf32(float x) {
    asm("cvt.rna.tf32.f32 %0, %0;" : "+f"(x));
    return x;
}
__device__ __forceinline__ float sigf(float x) { return 1.f / (1.f + __expf(-x)); }
__device__ __forceinline__ float tanhf_(float x) {
    float e = __expf(-2.f * fabsf(x));
    float t = (1.f - e) / (1.f + e);
    return copysignf(t, x);
}

// fp16 HMMA m16n8k16, fp32 accum
__device__ __forceinline__ void mma16(float* c, const unsigned* a, const unsigned* b) {
    asm volatile(
        "mma.sync.aligned.m16n8k16.row.col.f32.f16.f16.f32 "
        "{%0,%1,%2,%3}, {%4,%5,%6,%7}, {%8,%9}, {%0,%1,%2,%3};\n"
        : "+f"(c[0]), "+f"(c[1]), "+f"(c[2]), "+f"(c[3])
        : "r"(a[0]), "r"(a[1]), "r"(a[2]), "r"(a[3]), "r"(b[0]), "r"(b[1]));
}
// tf32 HMMA for k_xg
__device__ __forceinline__ void mma8(float* c, const unsigned* a, const unsigned* b) {
    asm volatile(
        "mma.sync.aligned.m16n8k8.row.col.f32.tf32.tf32.f32 "
        "{%0,%1,%2,%3}, {%4,%5,%6,%7}, {%8,%9}, {%0,%1,%2,%3};\n"
        : "+f"(c[0]), "+f"(c[1]), "+f"(c[2]), "+f"(c[3])
        : "r"(a[0]), "r"(a[1]), "r"(a[2]), "r"(a[3]), "r"(b[0]), "r"(b[1]));
}

// fine-grained producer poll: block tb needs CTAs 2tb and 2tb+1 at step >= s
__device__ __forceinline__ void poll_blk(int tb, int s, int lane) {
    if (lane < 2) {
        const int* f = d_pflag + (2 * tb + lane) * 8;
        int v;
        do {
            asm volatile("ld.acquire.gpu.global.b32 %0, [%1];" : "=r"(v) : "l"(f) : "memory");
        } while (v < s);
    }
    __syncwarp();
}

// ---------------- prep kernels ----------------
__global__ void k_prep_xt(const float* __restrict__ x, const float* __restrict__ mask,
                          const float* __restrict__ ti) {
    int idx = blockIdx.x * 256 + threadIdx.x;
    if (idx >= NS * NB * KP) return;
    int r = idx / KP, k = idx - r * KP;
    int s = r >> 7, b = r & 127;
    float v = 0.f;
    if (k < ND)            v = x[(b * NS + s) * ND + k];
    else if (k < 2 * ND)   v = mask[(b * NS + s) * ND + (k - ND)];
    else if (k == 2 * ND)  v = ti[b * NS + s];
    d_xt[idx] = to_tf32(v);
}

__global__ void k_prep_w(const float* __restrict__ wih, const float* __restrict__ whh,
                         const float* __restrict__ bih, const float* __restrict__ bhh) {
    int idx = blockIdx.x * 256 + threadIdx.x;
    if (idx < NG * KP) {
        int g = idx / KP, k = idx - g * KP;
        float v = (k < NIN) ? wih[g * NIN + k] : 0.f;
        d_wih[idx] = to_tf32(v);
    }
    if (idx < NG * NH) d_whh16[idx] = __float2half_rn(whh[idx]);
    if (idx < NG) d_bias[idx] = bih[idx] + bhh[idx];
    if (idx < 1024) d_pflag[idx] = 0;                          // reset flags each launch
    if (idx < 16384) ((uint4*)&d_h16[0][0])[idx] = make_uint4(0, 0, 0, 0);  // h0 = 0
}

// ---------------- XG GEMM (tf32 HMMA, fp16 output) ----------------
#define XA_STRIDE 28
#define XW_STRIDE 268
#define XG_SMEM (64 * XW_STRIDE * 4 + 2 * 128 * XA_STRIDE * 4)

__global__ void __launch_bounds__(256, 2) k_xg() {
    extern __shared__ float sm[];
    float* Wsm = sm;
    float* Asm = sm + 64 * XW_STRIDE;
    const int tid = threadIdx.x;
    const int bx = blockIdx.x;
    const int s = blockIdx.y;
    const int n0 = bx * 64;
    const int row0 = s * NB;

    unsigned wbase = smem_u32(Wsm);
    unsigned abase = smem_u32(Asm);

    for (int q = tid; q < 64 * 66; q += 256) {
        int r = q / 66, c = q - r * 66;
        cpa16(wbase + (unsigned)(r * XW_STRIDE + c * 4) * 4, d_wih + (n0 + r) * KP + c * 4);
    }
    for (int q = tid; q < 128 * 6; q += 256) {
        int r = q / 6, c = q - r * 6;
        cpa16(abase + (unsigned)(r * XA_STRIDE + c * 4) * 4, d_xt + (row0 + r) * KP + c * 4);
    }
    cp_commit();

    const int wid = tid >> 5, l = tid & 31;
    const int wm = wid >> 1, wn = wid & 1;
    const int lr = l >> 2, lc = l & 3;

    float acc[2][4][4];
#pragma unroll
    for (int i = 0; i < 2; i++)
#pragma unroll
        for (int j = 0; j < 4; j++)
#pragma unroll
            for (int k = 0; k < 4; k++) acc[i][j][k] = 0.f;

    for (int st = 0; st < 11; st++) {
        float* Ab = Asm + (st & 1) * 128 * XA_STRIDE;
        if (st < 10) {
            unsigned anb = abase + (unsigned)(((st + 1) & 1) * 128 * XA_STRIDE) * 4;
            int kb = (st + 1) * 24;
            for (int q = tid; q < 128 * 6; q += 256) {
                int r = q / 6, c = q - r * 6;
                cpa16(anb + (unsigned)(r * XA_STRIDE + c * 4) * 4,
                      d_xt + (row0 + r) * KP + kb + c * 4);
            }
            cp_commit();
            cp_wait1();
        } else {
            cp_wait0();
        }
        __syncthreads();
#pragma unroll
        for (int k8 = 0; k8 < 3; k8++) {
            int kk = k8 * 8;
            unsigned afr[2][4];
#pragma unroll
            for (int mt = 0; mt < 2; mt++) {
                const float* p = Ab + (wm * 32 + mt * 16 + lr) * XA_STRIDE + kk + lc;
                afr[mt][0] = __float_as_uint(p[0]);
                afr[mt][1] = __float_as_uint(p[8 * XA_STRIDE]);
                afr[mt][2] = __float_as_uint(p[4]);
                afr[mt][3] = __float_as_uint(p[8 * XA_STRIDE + 4]);
            }
#pragma unroll
            for (int nt = 0; nt < 4; nt++) {
                const float* p = Wsm + (wn * 32 + nt * 8 + lr) * XW_STRIDE + st * 24 + kk + lc;
                unsigned bfr[2] = { __float_as_uint(p[0]), __float_as_uint(p[4]) };
#pragma unroll
                for (int mt = 0; mt < 2; mt++) mma8(acc[mt][nt], afr[mt], bfr);
            }
        }
        __syncthreads();
    }

#pragma unroll
    for (int mt = 0; mt < 2; mt++) {
#pragma unroll
        for (int nt = 0; nt < 4; nt++) {
            int g = n0 + wn * 32 + nt * 8 + 2 * lc;
            float2 bias = *(const float2*)(d_bias + g);
#pragma unroll
            for (int p = 0; p < 2; p++) {
                int row = row0 + wm * 32 + mt * 16 + lr + p * 8;
                float ox = acc[mt][nt][2 * p + 0] + bias.x;
                float oy = acc[mt][nt][2 * p + 1] + bias.y;
                *(__half2*)(d_xg16 + (size_t)row * NG + g) = __floats2half2_rn(ox, oy);
            }
        }
    }
}

// ---------------- persistent recurrent kernel ----------------
// 128 CTAs (1/SM). CTA cid owns hidden units [8*cid, 8*cid+8) = 32 gate cols (N=32).
// 8 warps = 4 k-quarters (kw) x 2 m-halves (wm). Warp: M=64, N=32, K=256 (16 iters of k16).
// Fine-grained producer polling: iter block tb = kw*16+t needs only CTAs {2tb, 2tb+1};
// poll those 2 flags right before issuing the block's cp.async (pipelines steps, no
// global convergence). Union of polls over all warps covers all 128 producers before
// the reduce-__syncthreads, preserving the release/acquire + WAR correctness argument.
#define R_RING 4
#define R_RSTRIDE 40
#define R_W_OFF   0                      /* 65536 B: W slice */
#define R_A_OFF   65536                  /* 65536 B: 8 warps x 4 slots x 2048 B */
#define R_R0_OFF  131072                 /* 20480 B */
#define R_R1_OFF  151552                 /* 20480 B */
#define R_SMEM    172032

__global__ void __launch_bounds__(256, 1) k_rec() {
    extern __shared__ char smraw[];
    __half* Wsm = (__half*)(smraw + R_W_OFF);
    __half* Aring = (__half*)(smraw + R_A_OFF);
    float* R0 = (float*)(smraw + R_R0_OFF);
    float* R1 = (float*)(smraw + R_R1_OFF);

    const int tid = threadIdx.x;
    const int w = tid >> 5, lane = tid & 31;
    const int kw = w & 3, wm = w >> 2;
    const int cid = blockIdx.x;
    const int J0 = cid * 8;
    const int lr = lane >> 2, lc = lane & 3;

    __half* Aw = Aring + w * (R_RING * 1024);
    const unsigned awbase = smem_u32(Aw);

    // ---- W slice -> Wsm (permuted + swizzled) ----
    for (int q = tid; q < 32768; q += 256) {
        int n = q >> 10, k = q & 1023;
        int g = n >> 3, u = n & 7;
        __half v = d_whh16[(size_t)(g * 1024 + J0 + u) * NH + k];
        int tb = k >> 4, j = (k >> 1) & 7;
        int p = j & 3, hs = j >> 2;
        int slot = p ^ (n & 3);
        Wsm[tb * 512 + n * 16 + slot * 4 + hs * 2 + (k & 1)] = v;
    }
    __syncthreads();

    // persistent cell state: thread owns items idx = tid + 256q -> (m = idx>>2, u = idx&3)
    float creg[2][2] = {{0.f, 0.f}, {0.f, 0.f}};

    const int f_r[4] = { lane >> 1, (lane + 32) >> 1, (lane + 64) >> 1, (lane + 96) >> 1 };
    const int f_c = lane & 1;

    for (int s = 0; s < NS; s++) {
        const __half* hr = &d_h16[s & 1][0];
        __half* hw = &d_h16[(s + 1) & 1][0];
        const __half* xgS = d_xg16 + (size_t)s * NB * NG;

        // prefetch xg (consumed in epilogue) — independent of producer flags
        float2 xgr[2][4];
#pragma unroll
        for (int q = 0; q < 2; q++) {
            int idx = tid + q * 256;
            int m = idx >> 2, u = idx & 3;
            const __half* xp = xgS + (size_t)m * NG + J0 + 2 * u;
#pragma unroll
            for (int g = 0; g < 4; g++)
                xgr[q][g] = __half22float2(__ldg((const __half2*)(xp + g * 1024)));
        }

        float acc[4][4][4];
#pragma unroll
        for (int a = 0; a < 4; a++)
#pragma unroll
            for (int b = 0; b < 4; b++)
#pragma unroll
                for (int c = 0; c < 4; c++) acc[a][b][c] = 0.f;

        // prologue: fill slots 0..2 with t-blocks kw*16 + {0,1,2}, polling per block
#pragma unroll
        for (int pb = 0; pb < 3; pb++) {
            int tb = kw * 16 + pb;
            poll_blk(tb, s, lane);
#pragma unroll
            for (int i = 0; i < 4; i++) {
                const __half* src = hr + (size_t)(wm * 64 + f_r[i]) * NH + tb * 16 + f_c * 8;
                cpa16(awbase + (unsigned)(pb * 2048 + f_r[i] * 32 + f_c * 16), src);
            }
            cp_commit();
        }

        for (int t = 0; t < 16; t++) {
            __syncwarp();
            if (t < 13) {
                int ns = (t + 3) & 3;
                int tb = kw * 16 + t + 3;
                poll_blk(tb, s, lane);
#pragma unroll
                for (int i = 0; i < 4; i++) {
                    const __half* src = hr + (size_t)(wm * 64 + f_r[i]) * NH + tb * 16 + f_c * 8;
                    cpa16(awbase + (unsigned)(ns * 2048 + f_r[i] * 32 + f_c * 16), src);
                }
                cp_commit();
                cp_wait3();
            } else if (t == 13) {
                cp_wait2();
            } else if (t == 14) {
                cp_wait1();
            } else {
                cp_wait0();
            }
            __syncwarp();

            const __half* Ab = Aw + (t & 3) * 1024;
            const __half* Bt = Wsm + (kw * 16 + t) * 512;
            const int sl = (lc ^ (lr & 3)) * 4;

            unsigned bfr[4][2];
#pragma unroll
            for (int nt = 0; nt < 4; nt++) {
                uint2 v = *(const uint2*)(Bt + (nt * 8 + lr) * 16 + sl);
                bfr[nt][0] = v.x; bfr[nt][1] = v.y;
            }
            unsigned afr[4][4];
#pragma unroll
            for (int mt = 0; mt < 4; mt++) {
                uint2 lo = *(const uint2*)(Ab + (mt * 16 + lr) * 16 + sl);
                uint2 hi = *(const uint2*)(Ab + (mt * 16 + lr + 8) * 16 + sl);
                afr[mt][0] = lo.x; afr[mt][1] = hi.x;
                afr[mt][2] = lo.y; afr[mt][3] = hi.y;
            }
#pragma unroll
            for (int mt = 0; mt < 4; mt++)
#pragma unroll
                for (int nt = 0; nt < 4; nt++)
                    mma16(acc[mt][nt], afr[mt], bfr[nt]);
        }

        // ---- cross-warp k reduction ----
        __syncthreads();
        float* Rw = (kw < 2) ? R0 : R1;
        if ((kw & 1) == 0) {
#pragma unroll
            for (int mt = 0; mt < 4; mt++)
#pragma unroll
                for (int nt = 0; nt < 4; nt++)
#pragma unroll
                    for (int p = 0; p < 2; p++) {
                        int m = wm * 64 + mt * 16 + lr + p * 8;
                        *(float2*)(Rw + m * R_RSTRIDE + nt * 8 + 2 * lc) =
                            make_float2(acc[mt][nt][2 * p], acc[mt][nt][2 * p + 1]);
                    }
        }
        __syncthreads();
        if ((kw & 1) == 1) {
#pragma unroll
            for (int mt = 0; mt < 4; mt++)
#pragma unroll
                for (int nt = 0; nt < 4; nt++)
#pragma unroll
                    for (int p = 0; p < 2; p++) {
                        int m = wm * 64 + mt * 16 + lr + p * 8;
                        float2* dst = (float2*)(Rw + m * R_RSTRIDE + nt * 8 + 2 * lc);
                        float2 v = *dst;
                        v.x += acc[mt][nt][2 * p];
                        v.y += acc[mt][nt][2 * p + 1];
                        *dst = v;
                    }
        }
        __syncthreads();

        // ---- epilogue: gates + cell + permuted/swizzled h store ----
#pragma unroll
        for (int q = 0; q < 2; q++) {
            int idx = tid + q * 256;
            int m = idx >> 2, u = idx & 3;
            const float* r0 = R0 + m * R_RSTRIDE + 2 * u;
            const float* r1 = R1 + m * R_RSTRIDE + 2 * u;
            float2 gi = *(const float2*)(r0 +  0); float2 gi1 = *(const float2*)(r1 +  0);
            float2 gf = *(const float2*)(r0 +  8); float2 gf1 = *(const float2*)(r1 +  8);
            float2 gg = *(const float2*)(r0 + 16); float2 gg1 = *(const float2*)(r1 + 16);
            float2 go = *(const float2*)(r0 + 24); float2 go1 = *(const float2*)(r1 + 24);
            float h0, h1;
            {
                float iv = sigf(gi.x + gi1.x + xgr[q][0].x);
                float fv = sigf(gf.x + gf1.x + xgr[q][1].x);
                float gv = tanhf_(gg.x + gg1.x + xgr[q][2].x);
                float ov = sigf(go.x + go1.x + xgr[q][3].x);
                creg[q][0] = fv * creg[q][0] + iv * gv;
                h0 = ov * tanhf_(creg[q][0]);
            }
            {
                float iv = sigf(gi.y + gi1.y + xgr[q][0].y);
                float fv = sigf(gf.y + gf1.y + xgr[q][1].y);
                float gv = tanhf_(gg.y + gg1.y + xgr[q][2].y);
                float ov = sigf(go.y + go1.y + xgr[q][3].y);
                creg[q][1] = fv * creg[q][1] + iv * gv;
                h1 = ov * tanhf_(creg[q][1]);
            }
            int slot = u ^ (m & 3);
            char* dst = (char*)hw + (size_t)m * 2048 + (cid >> 1) * 32 + slot * 8 + (cid & 1) * 4;
            *(__half2*)dst = __floats2half2_rn(h0, h1);
        }

        // publish: h stores -> fence -> barrier -> release flag
        __threadfence();
        __syncthreads();
        if (tid == 0)
            asm volatile("st.release.gpu.global.b32 [%0], %1;"
                         :: "l"(d_pflag + cid * 8), "r"(s + 1) : "memory");
    }
}

// ---------------- final FC: out = h_last @ W_fc.T + b_fc (un-permute) ----------------
__global__ void k_fc(const float* __restrict__ wfc, const float* __restrict__ bfc,
                     float* __restrict__ out) {
    int idx = blockIdx.x * 256 + threadIdx.x;
    if (idx >= NB * NO) return;
    int b = idx >> 6, o = idx & 63;
    const __half* hrow = &d_h16[0][0] + (size_t)b * NH;   // NS even -> final h in buffer 0
    const float* wrow = wfc + o * NH;
    float sacc = 0.f;
#pragma unroll 4
    for (int k = 0; k < NH; k++) {
        int j = (k >> 1) & 7;
        int p = j & 3, hs = j >> 2;
        int hi = (k >> 4) * 16 + (p ^ (b & 3)) * 4 + hs * 2 + (k & 1);
        sacc += __half2float(hrow[hi]) * __ldg(wrow + k);
    }
    out[idx] = sacc + bfc[o];
}

// ---------------- launch ----------------
extern "C" void kernel_launch(void* const* d_in, const int* in_sizes, int n_in,
                              void* d_out, int out_size) {
    const float* x    = (const float*)d_in[0];
    const float* mask = (const float*)d_in[1];
    const float* ti   = (const float*)d_in[2];
    const float* wih  = (const float*)d_in[3];
    const float* whh  = (const float*)d_in[4];
    const float* bih  = (const float*)d_in[5];
    const float* bhh  = (const float*)d_in[6];
    const float* wfc  = (const float*)d_in[7];
    const float* bfc  = (const float*)d_in[8];
    float* out = (float*)d_out;

    cudaFuncSetAttribute(k_xg, cudaFuncAttributeMaxDynamicSharedMemorySize, XG_SMEM);
    cudaFuncSetAttribute(k_rec, cudaFuncAttributeMaxDynamicSharedMemorySize, R_SMEM);

    k_prep_xt<<<(NS * NB * KP + 255) / 256, 256>>>(x, mask, ti);
    k_prep_w<<<(NG * NH + 255) / 256, 256>>>(wih, whh, bih, bhh);
    k_xg<<<dim3(64, 512), 256, XG_SMEM>>>();
    k_rec<<<128, 256, R_SMEM>>>();
    k_fc<<<(NB * NO + 255) / 256, 256>>>(wfc, bfc, out);
}

// round 12
// speedup vs baseline: 1.4674x; 1.4674x over previous
#include <cuda_runtime.h>
#include <cuda_fp16.h>
#include <cstdint>
#include <cstddef>

#define NB 128
#define NS 512
#define ND 128
#define NH 1024
#define NO 64
#define NIN 257
#define KP2 272       // fp16-padded input size (17 x k16)
#define NG 4096

// ---------------- device scratch ----------------
__device__ __align__(16) __half d_xt16[NS * NB * KP2];
__device__ __align__(16) __half d_wih16[NG * KP2];
__device__ __align__(16) __half d_whh16[NG * NH];
__device__ __align__(16) float d_bias[NG];
__device__ __align__(16) __half d_xg16[(size_t)NS * NB * NG];  // fp16 input-gate precompute
__device__ __align__(1024) __half d_h16[2][NB * NH];   // permuted+swizzled layout
__device__ __align__(16) int d_pflag[128 * 8];         // producer step flags (stride 8)

// ---------------- helpers ----------------
__device__ __forceinline__ unsigned smem_u32(const void* p) {
    return (unsigned)__cvta_generic_to_shared(p);
}
__device__ __forceinline__ void cpa16(unsigned s, const void* g) {
    asm volatile("cp.async.cg.shared.global [%0], [%1], 16;\n" :: "r"(s), "l"(g));
}
__device__ __forceinline__ void cp_commit() { asm volatile("cp.async.commit_group;\n"); }
__device__ __forceinline__ void cp_wait0() { asm volatile("cp.async.wait_group 0;\n" ::: "memory"); }
__device__ __forceinline__ void cp_wait1() { asm volatile("cp.async.wait_group 1;\n" ::: "memory"); }
__device__ __forceinline__ void cp_wait2() { asm volatile("cp.async.wait_group 2;\n" ::: "memory"); }
__device__ __forceinline__ void cp_wait3() { asm volatile("cp.async.wait_group 3;\n" ::: "memory"); }

__device__ __forceinline__ float sigf(float x) { return 1.f / (1.f + __expf(-x)); }
__device__ __forceinline__ float tanhf_(float x) {
    float e = __expf(-2.f * fabsf(x));
    float t = (1.f - e) / (1.f + e);
    return copysignf(t, x);
}

// fp16 HMMA m16n8k16, fp32 accum
__device__ __forceinline__ void mma16(float* c, const unsigned* a, const unsigned* b) {
    asm volatile(
        "mma.sync.aligned.m16n8k16.row.col.f32.f16.f16.f32 "
        "{%0,%1,%2,%3}, {%4,%5,%6,%7}, {%8,%9}, {%0,%1,%2,%3};\n"
        : "+f"(c[0]), "+f"(c[1]), "+f"(c[2]), "+f"(c[3])
        : "r"(a[0]), "r"(a[1]), "r"(a[2]), "r"(a[3]), "r"(b[0]), "r"(b[1]));
}

// ---------------- prep kernels ----------------
__global__ void k_prep_xt(const float* __restrict__ x, const float* __restrict__ mask,
                          const float* __restrict__ ti) {
    int idx = blockIdx.x * 256 + threadIdx.x;
    if (idx >= NS * NB * KP2) return;
    int r = idx / KP2, k = idx - r * KP2;
    int s = r >> 7, b = r & 127;
    float v = 0.f;
    if (k < ND)            v = x[(b * NS + s) * ND + k];
    else if (k < 2 * ND)   v = mask[(b * NS + s) * ND + (k - ND)];
    else if (k == 2 * ND)  v = ti[b * NS + s];
    d_xt16[idx] = __float2half_rn(v);
}

__global__ void k_prep_w(const float* __restrict__ wih, const float* __restrict__ whh,
                         const float* __restrict__ bih, const float* __restrict__ bhh) {
    int idx = blockIdx.x * 256 + threadIdx.x;
    if (idx < NG * KP2) {
        int g = idx / KP2, k = idx - g * KP2;
        float v = (k < NIN) ? wih[g * NIN + k] : 0.f;
        d_wih16[idx] = __float2half_rn(v);
    }
    if (idx < NG * NH) d_whh16[idx] = __float2half_rn(whh[idx]);
    if (idx < NG) d_bias[idx] = bih[idx] + bhh[idx];
    if (idx < 1024) d_pflag[idx] = 0;                          // reset flags each launch
    if (idx < 16384) ((uint4*)&d_h16[0][0])[idx] = make_uint4(0, 0, 0, 0);  // h0 = 0
}

// ---------------- XG GEMM (fp16 HMMA m16n8k16) ----------------
// CTA tile: M=128 (batch, s fixed) x N=64, K=272 (17 k16 blocks), A tile fully resident.
// Stride 280 halves: word index = row*140 + tb*8 + lc -> all 32 lanes distinct banks.
#define X_STRIDE 280
#define XG_SMEM ((64 + 128) * X_STRIDE * 2)    /* 107520 B */

__global__ void __launch_bounds__(256, 2) k_xg() {
    extern __shared__ __half smh[];
    __half* Wsm = smh;                         // [64][280]
    __half* Asm = smh + 64 * X_STRIDE;         // [128][280]
    const int tid = threadIdx.x;
    const int n0 = blockIdx.x * 64;
    const int row0 = blockIdx.y * NB;

    unsigned wb = smem_u32(Wsm);
    unsigned ab = smem_u32(Asm);

    // W: 64 rows x 34 16B-chunks; A: 128 rows x 34 chunks (272 halves = 544 B/row)
    for (int q = tid; q < 64 * 34; q += 256) {
        int r = q / 34, c = q - r * 34;
        cpa16(wb + (unsigned)(r * X_STRIDE * 2 + c * 16), d_wih16 + (n0 + r) * KP2 + c * 8);
    }
    for (int q = tid; q < 128 * 34; q += 256) {
        int r = q / 34, c = q - r * 34;
        cpa16(ab + (unsigned)(r * X_STRIDE * 2 + c * 16), d_xt16 + (row0 + r) * KP2 + c * 8);
    }
    cp_commit();
    cp_wait0();
    __syncthreads();

    const int wid = tid >> 5, l = tid & 31;
    const int wm = wid >> 1, wn = wid & 1;     // 4 x 2 warps, warp tile 32x32
    const int lr = l >> 2, lc = l & 3;

    float acc[2][4][4];
#pragma unroll
    for (int i = 0; i < 2; i++)
#pragma unroll
        for (int j = 0; j < 4; j++)
#pragma unroll
            for (int k = 0; k < 4; k++) acc[i][j][k] = 0.f;

    for (int tb = 0; tb < 17; tb++) {
        const int kb = tb * 16 + 2 * lc;
        unsigned afr[2][4];
#pragma unroll
        for (int mt = 0; mt < 2; mt++) {
            const __half* p = Asm + (wm * 32 + mt * 16 + lr) * X_STRIDE + kb;
            afr[mt][0] = *(const unsigned*)(p);
            afr[mt][1] = *(const unsigned*)(p + 8 * X_STRIDE);
            afr[mt][2] = *(const unsigned*)(p + 8);
            afr[mt][3] = *(const unsigned*)(p + 8 * X_STRIDE + 8);
        }
#pragma unroll
        for (int nt = 0; nt < 4; nt++) {
            const __half* p = Wsm + (wn * 32 + nt * 8 + lr) * X_STRIDE + kb;
            unsigned bfr[2] = { *(const unsigned*)(p), *(const unsigned*)(p + 8) };
#pragma unroll
            for (int mt = 0; mt < 2; mt++) mma16(acc[mt][nt], afr[mt], bfr);
        }
    }

    // epilogue: add bias, store fp16
#pragma unroll
    for (int mt = 0; mt < 2; mt++) {
#pragma unroll
        for (int nt = 0; nt < 4; nt++) {
            int g = n0 + wn * 32 + nt * 8 + 2 * lc;
            float2 bias = *(const float2*)(d_bias + g);
#pragma unroll
            for (int p = 0; p < 2; p++) {
                int row = row0 + wm * 32 + mt * 16 + lr + p * 8;
                float ox = acc[mt][nt][2 * p + 0] + bias.x;
                float oy = acc[mt][nt][2 * p + 1] + bias.y;
                *(__half2*)(d_xg16 + (size_t)row * NG + g) = __floats2half2_rn(ox, oy);
            }
        }
    }
}

// ---------------- persistent recurrent kernel (R9 structure) ----------------
// 128 CTAs (1/SM). CTA cid owns hidden units [8*cid, 8*cid+8) = 32 gate cols (N=32).
// 8 warps = 4 k-quarters (kw) x 2 m-halves (wm). Warp: M=64, N=32, K=256 (16 iters of k16).
// Bulk warp-parallel acquire poll of the 32 producer CTAs of this warp's k-quarter.
#define R_RING 4
#define R_RSTRIDE 40
#define R_W_OFF   0                      /* 65536 B: W slice */
#define R_A_OFF   65536                  /* 65536 B: 8 warps x 4 slots x 2048 B */
#define R_R0_OFF  131072                 /* 20480 B */
#define R_R1_OFF  151552                 /* 20480 B */
#define R_SMEM    172032

__global__ void __launch_bounds__(256, 1) k_rec() {
    extern __shared__ char smraw[];
    __half* Wsm = (__half*)(smraw + R_W_OFF);
    __half* Aring = (__half*)(smraw + R_A_OFF);
    float* R0 = (float*)(smraw + R_R0_OFF);
    float* R1 = (float*)(smraw + R_R1_OFF);

    const int tid = threadIdx.x;
    const int w = tid >> 5, lane = tid & 31;
    const int kw = w & 3, wm = w >> 2;
    const int cid = blockIdx.x;
    const int J0 = cid * 8;
    const int lr = lane >> 2, lc = lane & 3;

    __half* Aw = Aring + w * (R_RING * 1024);
    const unsigned awbase = smem_u32(Aw);

    // ---- W slice -> Wsm (permuted + swizzled) ----
    for (int q = tid; q < 32768; q += 256) {
        int n = q >> 10, k = q & 1023;
        int g = n >> 3, u = n & 7;
        __half v = d_whh16[(size_t)(g * 1024 + J0 + u) * NH + k];
        int tb = k >> 4, j = (k >> 1) & 7;
        int p = j & 3, hs = j >> 2;
        int slot = p ^ (n & 3);
        Wsm[tb * 512 + n * 16 + slot * 4 + hs * 2 + (k & 1)] = v;
    }
    __syncthreads();

    // persistent cell state: thread owns items idx = tid + 256q -> (m = idx>>2, u = idx&3)
    float creg[2][2] = {{0.f, 0.f}, {0.f, 0.f}};

    const int f_r[4] = { lane >> 1, (lane + 32) >> 1, (lane + 64) >> 1, (lane + 96) >> 1 };
    const int f_c = lane & 1;
    const int* myflag = d_pflag + (32 * kw + lane) * 8;

    for (int s = 0; s < NS; s++) {
        const __half* hr = &d_h16[s & 1][0];
        __half* hw = &d_h16[(s + 1) & 1][0];
        const __half* xgS = d_xg16 + (size_t)s * NB * NG;

        // prefetch xg (consumed in epilogue)
        float2 xgr[2][4];
#pragma unroll
        for (int q = 0; q < 2; q++) {
            int idx = tid + q * 256;
            int m = idx >> 2, u = idx & 3;
            const __half* xp = xgS + (size_t)m * NG + J0 + 2 * u;
#pragma unroll
            for (int g = 0; g < 4; g++)
                xgr[q][g] = __half22float2(__ldg((const __half2*)(xp + g * 1024)));
        }

        // ---- bulk acquire-poll: all 32 producers of this warp's k-quarter at step >= s ----
        {
            int v;
            do {
                asm volatile("ld.acquire.gpu.global.b32 %0, [%1];"
                             : "=r"(v) : "l"(myflag) : "memory");
            } while (__any_sync(0xFFFFFFFFu, v < s));
        }

        float acc[4][4][4];
#pragma unroll
        for (int a = 0; a < 4; a++)
#pragma unroll
            for (int b = 0; b < 4; b++)
#pragma unroll
                for (int c = 0; c < 4; c++) acc[a][b][c] = 0.f;

        // prologue: fill slots 0..2 with t-blocks kw*16 + {0,1,2}
#pragma unroll
        for (int pb = 0; pb < 3; pb++) {
            int tb = kw * 16 + pb;
#pragma unroll
            for (int i = 0; i < 4; i++) {
                const __half* src = hr + (size_t)(wm * 64 + f_r[i]) * NH + tb * 16 + f_c * 8;
                cpa16(awbase + (unsigned)(pb * 2048 + f_r[i] * 32 + f_c * 16), src);
            }
            cp_commit();
        }

        for (int t = 0; t < 16; t++) {
            __syncwarp();
            if (t < 13) {
                int ns = (t + 3) & 3;
                int tb = kw * 16 + t + 3;
#pragma unroll
                for (int i = 0; i < 4; i++) {
                    const __half* src = hr + (size_t)(wm * 64 + f_r[i]) * NH + tb * 16 + f_c * 8;
                    cpa16(awbase + (unsigned)(ns * 2048 + f_r[i] * 32 + f_c * 16), src);
                }
                cp_commit();
                cp_wait3();
            } else if (t == 13) {
                cp_wait2();
            } else if (t == 14) {
                cp_wait1();
            } else {
                cp_wait0();
            }
            __syncwarp();

            const __half* Ab = Aw + (t & 3) * 1024;
            const __half* Bt = Wsm + (kw * 16 + t) * 512;
            const int sl = (lc ^ (lr & 3)) * 4;

            unsigned bfr[4][2];
#pragma unroll
            for (int nt = 0; nt < 4; nt++) {
                uint2 v = *(const uint2*)(Bt + (nt * 8 + lr) * 16 + sl);
                bfr[nt][0] = v.x; bfr[nt][1] = v.y;
            }
            unsigned afr[4][4];
#pragma unroll
            for (int mt = 0; mt < 4; mt++) {
                uint2 lo = *(const uint2*)(Ab + (mt * 16 + lr) * 16 + sl);
                uint2 hi = *(const uint2*)(Ab + (mt * 16 + lr + 8) * 16 + sl);
                afr[mt][0] = lo.x; afr[mt][1] = hi.x;
                afr[mt][2] = lo.y; afr[mt][3] = hi.y;
            }
#pragma unroll
            for (int mt = 0; mt < 4; mt++)
#pragma unroll
                for (int nt = 0; nt < 4; nt++)
                    mma16(acc[mt][nt], afr[mt], bfr[nt]);
        }

        // ---- cross-warp k reduction ----
        __syncthreads();
        float* Rw = (kw < 2) ? R0 : R1;
        if ((kw & 1) == 0) {
#pragma unroll
            for (int mt = 0; mt < 4; mt++)
#pragma unroll
                for (int nt = 0; nt < 4; nt++)
#pragma unroll
                    for (int p = 0; p < 2; p++) {
                        int m = wm * 64 + mt * 16 + lr + p * 8;
                        *(float2*)(Rw + m * R_RSTRIDE + nt * 8 + 2 * lc) =
                            make_float2(acc[mt][nt][2 * p], acc[mt][nt][2 * p + 1]);
                    }
        }
        __syncthreads();
        if ((kw & 1) == 1) {
#pragma unroll
            for (int mt = 0; mt < 4; mt++)
#pragma unroll
                for (int nt = 0; nt < 4; nt++)
#pragma unroll
                    for (int p = 0; p < 2; p++) {
                        int m = wm * 64 + mt * 16 + lr + p * 8;
                        float2* dst = (float2*)(Rw + m * R_RSTRIDE + nt * 8 + 2 * lc);
                        float2 v = *dst;
                        v.x += acc[mt][nt][2 * p];
                        v.y += acc[mt][nt][2 * p + 1];
                        *dst = v;
                    }
        }
        __syncthreads();

        // ---- epilogue: gates + cell + permuted/swizzled h store ----
#pragma unroll
        for (int q = 0; q < 2; q++) {
            int idx = tid + q * 256;
            int m = idx >> 2, u = idx & 3;
            const float* r0 = R0 + m * R_RSTRIDE + 2 * u;
            const float* r1 = R1 + m * R_RSTRIDE + 2 * u;
            float2 gi = *(const float2*)(r0 +  0); float2 gi1 = *(const float2*)(r1 +  0);
            float2 gf = *(const float2*)(r0 +  8); float2 gf1 = *(const float2*)(r1 +  8);
            float2 gg = *(const float2*)(r0 + 16); float2 gg1 = *(const float2*)(r1 + 16);
            float2 go = *(const float2*)(r0 + 24); float2 go1 = *(const float2*)(r1 + 24);
            float h0, h1;
            {
                float iv = sigf(gi.x + gi1.x + xgr[q][0].x);
                float fv = sigf(gf.x + gf1.x + xgr[q][1].x);
                float gv = tanhf_(gg.x + gg1.x + xgr[q][2].x);
                float ov = sigf(go.x + go1.x + xgr[q][3].x);
                creg[q][0] = fv * creg[q][0] + iv * gv;
                h0 = ov * tanhf_(creg[q][0]);
            }
            {
                float iv = sigf(gi.y + gi1.y + xgr[q][0].y);
                float fv = sigf(gf.y + gf1.y + xgr[q][1].y);
                float gv = tanhf_(gg.y + gg1.y + xgr[q][2].y);
                float ov = sigf(go.y + go1.y + xgr[q][3].y);
                creg[q][1] = fv * creg[q][1] + iv * gv;
                h1 = ov * tanhf_(creg[q][1]);
            }
            int slot = u ^ (m & 3);
            char* dst = (char*)hw + (size_t)m * 2048 + (cid >> 1) * 32 + slot * 8 + (cid & 1) * 4;
            *(__half2*)dst = __floats2half2_rn(h0, h1);
        }

        // publish: h stores -> release fence -> barrier -> release flag
        asm volatile("fence.acq_rel.gpu;" ::: "memory");
        __syncthreads();
        if (tid == 0)
            asm volatile("st.release.gpu.global.b32 [%0], %1;"
                         :: "l"(d_pflag + cid * 8), "r"(s + 1) : "memory");
    }
}

// ---------------- final FC: out = h_last @ W_fc.T + b_fc (un-permute) ----------------
__global__ void k_fc(const float* __restrict__ wfc, const float* __restrict__ bfc,
                     float* __restrict__ out) {
    int idx = blockIdx.x * 256 + threadIdx.x;
    if (idx >= NB * NO) return;
    int b = idx >> 6, o = idx & 63;
    const __half* hrow = &d_h16[0][0] + (size_t)b * NH;   // NS even -> final h in buffer 0
    const float* wrow = wfc + o * NH;
    float sacc = 0.f;
#pragma unroll 4
    for (int k = 0; k < NH; k++) {
        int j = (k >> 1) & 7;
        int p = j & 3, hs = j >> 2;
        int hi = (k >> 4) * 16 + (p ^ (b & 3)) * 4 + hs * 2 + (k & 1);
        sacc += __half2float(hrow[hi]) * __ldg(wrow + k);
    }
    out[idx] = sacc + bfc[o];
}

// ---------------- launch ----------------
extern "C" void kernel_launch(void* const* d_in, const int* in_sizes, int n_in,
                              void* d_out, int out_size) {
    const float* x    = (const float*)d_in[0];
    const float* mask = (const float*)d_in[1];
    const float* ti   = (const float*)d_in[2];
    const float* wih  = (const float*)d_in[3];
    const float* whh  = (const float*)d_in[4];
    const float* bih  = (const float*)d_in[5];
    const float* bhh  = (const float*)d_in[6];
    const float* wfc  = (const float*)d_in[7];
    const float* bfc  = (const float*)d_in[8];
    float* out = (float*)d_out;

    cudaFuncSetAttribute(k_xg, cudaFuncAttributeMaxDynamicSharedMemorySize, XG_SMEM);
    cudaFuncSetAttribute(k_rec, cudaFuncAttributeMaxDynamicSharedMemorySize, R_SMEM);

    k_prep_xt<<<(NS * NB * KP2 + 255) / 256, 256>>>(x, mask, ti);
    k_prep_w<<<(NG * NH + 255) / 256, 256>>>(wih, whh, bih, bhh);
    k_xg<<<dim3(64, 512), 256, XG_SMEM>>>();
    k_rec<<<128, 256, R_SMEM>>>();
    k_fc<<<(NB * NO + 255) / 256, 256>>>(wfc, bfc, out);
}